// round 2
// baseline (speedup 1.0000x reference)
#include <cuda_runtime.h>
#include <cstdint>

#define PI_F 3.14159265358979323846f
#define CUTOFF_F 5.0f
#define MAX_N 50000

// scratch for scalar_out = silu(ns@W1+b1)@W2+b2, shape [N,192]
__device__ float g_so[(size_t)MAX_N * 192];
__device__ int g_edge_is64;

// packed f32x2 fma: d.lo=a.lo*b.lo+c.lo ; d.hi=a.hi*b.hi+c.hi
__device__ __forceinline__ unsigned long long fma2(unsigned long long a,
                                                   unsigned long long b,
                                                   unsigned long long c) {
    unsigned long long d;
    asm("fma.rn.f32x2 %0, %1, %2, %3;" : "=l"(d) : "l"(a), "l"(b), "l"(c));
    return d;
}

// ---------------------------------------------------------------------------
// Kernel 0: detect whether edge array is int64 (odd int32 words all zero)
// or int32 (odd words are random indices).
// ---------------------------------------------------------------------------
__global__ void detect_kernel(const int* __restrict__ edge32, int n_check)
{
    __shared__ int any_nonzero;
    if (threadIdx.x == 0) any_nonzero = 0;
    __syncthreads();
    for (int i = threadIdx.x; i < n_check; i += blockDim.x)
        if (edge32[2 * i + 1] != 0) any_nonzero = 1;
    __syncthreads();
    if (threadIdx.x == 0) g_edge_is64 = (any_nonzero == 0) ? 1 : 0;
}

// ---------------------------------------------------------------------------
// Kernel 1: node GEMM. 32 nodes/block, 128 threads.
// Also writes node_scalar into out_s (residual init).
// ---------------------------------------------------------------------------
__global__ void __launch_bounds__(128) gemm_kernel(
    const float* __restrict__ ns, const float* __restrict__ W1,
    const float* __restrict__ b1, const float* __restrict__ W2,
    const float* __restrict__ b2, float* __restrict__ out_s, int N)
{
    __shared__ __align__(16) float W1s[64 * 64];
    __shared__ __align__(16) float xs[32 * 64];
    __shared__ __align__(16) float hs[32 * 64];
    __shared__ float b1s[64];
    __shared__ float b2s[192];

    int tid = threadIdx.x;
    for (int i = tid; i < 4096; i += 128) W1s[i] = W1[i];
    if (tid < 64) b1s[tid] = b1[tid];
    if (tid < 64) {
        b2s[tid] = b2[tid];
        b2s[tid + 64] = b2[tid + 64];
        b2s[tid + 128] = b2[tid + 128];
    }
    int base = blockIdx.x * 32;
    for (int i = tid; i < 32 * 64; i += 128) {
        int node = base + (i >> 6);
        float v = (node < N) ? ns[(size_t)base * 64 + i] : 0.f;
        xs[i] = v;
        if (node < N) out_s[(size_t)base * 64 + i] = v;  // residual init
    }
    __syncthreads();

    int fg = tid & 15;   // feature group: fb = fg*4
    int ng = tid >> 4;   // node group: n0 = ng*4 (8 groups x 4 = 32 nodes)
    int fb = fg * 4, n0 = ng * 4;

    // phase 1: h = silu(x @ W1 + b1)
    float acc[4][4];
#pragma unroll
    for (int g = 0; g < 4; g++)
#pragma unroll
        for (int k = 0; k < 4; k++) acc[g][k] = 0.f;
#pragma unroll 8
    for (int i = 0; i < 64; i++) {
        float4 w = reinterpret_cast<const float4*>(W1s)[i * 16 + fg];
#pragma unroll
        for (int g = 0; g < 4; g++) {
            float x = xs[(n0 + g) * 64 + i];
            acc[g][0] = fmaf(x, w.x, acc[g][0]);
            acc[g][1] = fmaf(x, w.y, acc[g][1]);
            acc[g][2] = fmaf(x, w.z, acc[g][2]);
            acc[g][3] = fmaf(x, w.w, acc[g][3]);
        }
    }
#pragma unroll
    for (int g = 0; g < 4; g++) {
        float4 hv;
        float* hp = (float*)&hv;
#pragma unroll
        for (int k = 0; k < 4; k++) {
            float v = acc[g][k] + b1s[fb + k];
            hp[k] = v / (1.f + expf(-v));
        }
        reinterpret_cast<float4*>(&hs[(n0 + g) * 64 + fb])[0] = hv;
    }
    __syncthreads();

    // phase 2: so = h @ W2 + b2  (W2 read through L1, 3 passes of 64 cols)
#pragma unroll 1
    for (int p = 0; p < 3; p++) {
#pragma unroll
        for (int g = 0; g < 4; g++)
#pragma unroll
            for (int k = 0; k < 4; k++) acc[g][k] = 0.f;
#pragma unroll 8
        for (int i = 0; i < 64; i++) {
            float4 w = __ldg(reinterpret_cast<const float4*>(W2) + i * 48 + p * 16 + fg);
#pragma unroll
            for (int g = 0; g < 4; g++) {
                float h = hs[(n0 + g) * 64 + i];
                acc[g][0] = fmaf(h, w.x, acc[g][0]);
                acc[g][1] = fmaf(h, w.y, acc[g][1]);
                acc[g][2] = fmaf(h, w.z, acc[g][2]);
                acc[g][3] = fmaf(h, w.w, acc[g][3]);
            }
        }
#pragma unroll
        for (int g = 0; g < 4; g++) {
            int node = base + n0 + g;
            if (node < N) {
                float4 ov;
                float* op = (float*)&ov;
#pragma unroll
                for (int k = 0; k < 4; k++) op[k] = acc[g][k] + b2s[p * 64 + fb + k];
                reinterpret_cast<float4*>(&g_so[(size_t)node * 192 + p * 64 + fb])[0] = ov;
            }
        }
    }
}

// ---------------------------------------------------------------------------
// Kernel 2: init vector half of output with node_vector
// ---------------------------------------------------------------------------
__global__ void copy_vec_kernel(const float4* __restrict__ src,
                                float4* __restrict__ dst, int n4)
{
    int i = blockIdx.x * blockDim.x + threadIdx.x;
    if (i < n4) dst[i] = src[i];
}

// ---------------------------------------------------------------------------
// Kernel 3: edge kernel. 192 threads (thread = feature), 32 edges per tile.
// ---------------------------------------------------------------------------
__global__ void __launch_bounds__(192) edge_kernel(
    const void* __restrict__ edge_raw, const float* __restrict__ ediff,
    const float* __restrict__ edist, const float* __restrict__ Wf,
    const float* __restrict__ bf, const float* __restrict__ nv,
    float* __restrict__ out_s, float* __restrict__ out_v,
    int E, int ntiles)
{
    __shared__ __align__(16) float rbf_s[20 * 32];  // [n][e]
    __shared__ __align__(16) float fo_s[32 * 192];  // [e][f]
    __shared__ float d_s[32], inv_s[32], cut_s[32];
    __shared__ float unit_s[3 * 32];                // [d3][e]
    __shared__ int src_s[32], dst_s[32];

    int tid = threadIdx.x;  // = feature f, 0..191
    int is64 = g_edge_is64;
    const int* e32 = (const int*)edge_raw;
    const long long* e64 = (const long long*)edge_raw;

    // Wf column for this feature, packed (w,w) for f32x2; bf for this feature
    unsigned long long wf2[20];
#pragma unroll
    for (int n = 0; n < 20; n++) {
        unsigned int u = __float_as_uint(__ldg(&Wf[n * 192 + tid]));
        wf2[n] = ((unsigned long long)u << 32) | (unsigned long long)u;
    }
    float bf_r = __ldg(&bf[tid]);

    int c = tid & 63;   // vector channel
    int d3 = tid >> 6;  // vector component 0..2 (constant per warp)

    for (int t = blockIdx.x; t < ntiles; t += gridDim.x) {
        int ebase = t * 32;
        if (tid < 32) {
            int e = ebase + tid;
            if (e < E) {
                float d = edist[e];
                float inv = 1.f / d;
                d_s[tid] = d;
                inv_s[tid] = inv;
                cut_s[tid] = (d < CUTOFF_F) ? 0.5f * (cosf((PI_F / CUTOFF_F) * d) + 1.f) : 0.f;
                int sv, dv;
                if (is64) {
                    dv = (int)e64[2 * (size_t)e + 0];
                    sv = (int)e64[2 * (size_t)e + 1];
                } else {
                    dv = e32[2 * (size_t)e + 0];
                    sv = e32[2 * (size_t)e + 1];
                }
                src_s[tid] = sv;
                dst_s[tid] = dv;
                unit_s[0 * 32 + tid] = ediff[3 * (size_t)e + 0] * inv;
                unit_s[1 * 32 + tid] = ediff[3 * (size_t)e + 1] * inv;
                unit_s[2 * 32 + tid] = ediff[3 * (size_t)e + 2] * inv;
            } else {
                d_s[tid] = 1.f; inv_s[tid] = 0.f; cut_s[tid] = 0.f;
                src_s[tid] = 0; dst_s[tid] = 0;
                unit_s[tid] = unit_s[32 + tid] = unit_s[64 + tid] = 0.f;
            }
        }
        __syncthreads();

        // rbf: sin(d * n * pi / cutoff) / d   for n=1..20
        for (int idx = tid; idx < 640; idx += 192) {
            int n = idx >> 5, e = idx & 31;
            rbf_s[idx] = sinf(d_s[e] * ((float)(n + 1) * (PI_F / CUTOFF_F))) * inv_s[e];
        }
        __syncthreads();

        // filter = (rbf @ Wf + bf) * cut * scalar_out[src]  (f32x2, 4 edges at a time)
#pragma unroll
        for (int g = 0; g < 8; g++) {
            unsigned long long a01 = 0ull, a23 = 0ull;
#pragma unroll
            for (int n = 0; n < 20; n++) {
                ulonglong2 rr = *reinterpret_cast<const ulonglong2*>(&rbf_s[n * 32 + g * 4]);
                a01 = fma2(rr.x, wf2[n], a01);
                a23 = fma2(rr.y, wf2[n], a23);
            }
            float fv[4];
            fv[0] = __uint_as_float((unsigned)a01);
            fv[1] = __uint_as_float((unsigned)(a01 >> 32));
            fv[2] = __uint_as_float((unsigned)a23);
            fv[3] = __uint_as_float((unsigned)(a23 >> 32));
#pragma unroll
            for (int j = 0; j < 4; j++) {
                int e = g * 4 + j;
                float sov = __ldg(&g_so[(size_t)src_s[e] * 192 + tid]);
                fo_s[e * 192 + tid] = (fv[j] + bf_r) * cut_s[e] * sov;
            }
        }
        __syncthreads();

        // messages + scatter-add
#pragma unroll 4
        for (int e = 0; e < 32; e++) {
            int src = src_s[e], dst = dst_s[e];
            float gs = fo_s[e * 192 + c];
            float ge = fo_s[e * 192 + 64 + c];
            float u = unit_s[d3 * 32 + e];
            float nvv = __ldg(&nv[(size_t)src * 192 + d3 * 64 + c]);
            atomicAdd(&out_v[(size_t)dst * 192 + d3 * 64 + c], fmaf(nvv, gs, ge * u));
            if (tid < 64) {
                atomicAdd(&out_s[(size_t)dst * 64 + tid], fo_s[e * 192 + 128 + tid]);
            }
        }
        __syncthreads();
    }
}

// ---------------------------------------------------------------------------
extern "C" void kernel_launch(void* const* d_in, const int* in_sizes, int n_in,
                              void* d_out, int out_size)
{
    const float* ns     = (const float*)d_in[0];
    const float* nvec   = (const float*)d_in[1];
    const void*  ed     = (const void*)d_in[2];
    const float* ediff  = (const float*)d_in[3];
    const float* edist  = (const float*)d_in[4];
    const float* W1     = (const float*)d_in[5];
    const float* b1     = (const float*)d_in[6];
    const float* W2     = (const float*)d_in[7];
    const float* b2     = (const float*)d_in[8];
    const float* Wf     = (const float*)d_in[9];
    const float* bf     = (const float*)d_in[10];

    int N = in_sizes[0] / 64;
    int E = in_sizes[4];  // edge_dist has E elements

    float* out_s = (float*)d_out;
    float* out_v = out_s + (size_t)N * 64;

    // 0) detect edge index dtype (int32 vs int64)
    int n_check = (2 * E < 1024) ? 2 * E / 2 : 1024;
    detect_kernel<<<1, 256>>>((const int*)ed, n_check);

    // 1) node MLP (+ scalar residual init)
    gemm_kernel<<<(N + 31) / 32, 128>>>(ns, W1, b1, W2, b2, out_s, N);

    // 2) vector residual init
    int n4 = (N * 192) / 4;
    copy_vec_kernel<<<(n4 + 255) / 256, 256>>>(
        (const float4*)nvec, (float4*)out_v, n4);

    // 3) edge messages + scatter
    int ntiles = (E + 31) / 32;
    int grid = ntiles < 2368 ? ntiles : 2368;
    edge_kernel<<<grid, 192>>>(ed, ediff, edist, Wf, bf, nvec,
                               out_s, out_v, E, ntiles);
}

// round 3
// speedup vs baseline: 1.3661x; 1.3661x over previous
#include <cuda_runtime.h>
#include <cstdint>

#define PI_F 3.14159265358979323846f
#define CUTOFF_F 5.0f
#define MAX_N 50000

// scratch for scalar_out = silu(ns@W1+b1)@W2+b2, shape [N,192]
__device__ float g_so[(size_t)MAX_N * 192];
__device__ int g_edge_is64;

// packed f32x2 fma: d.lo=a.lo*b.lo+c.lo ; d.hi=a.hi*b.hi+c.hi
__device__ __forceinline__ unsigned long long fma2(unsigned long long a,
                                                   unsigned long long b,
                                                   unsigned long long c) {
    unsigned long long d;
    asm("fma.rn.f32x2 %0, %1, %2, %3;" : "=l"(d) : "l"(a), "l"(b), "l"(c));
    return d;
}

__device__ __forceinline__ unsigned long long pack2(float w) {
    unsigned long long r;
    asm("mov.b64 %0, {%1, %1};" : "=l"(r) : "f"(w));
    return r;
}

// ---------------------------------------------------------------------------
// Kernel 0: detect whether edge array is int64 (odd int32 words all zero)
// ---------------------------------------------------------------------------
__global__ void detect_kernel(const int* __restrict__ edge32, int n_check)
{
    __shared__ int any_nonzero;
    if (threadIdx.x == 0) any_nonzero = 0;
    __syncthreads();
    for (int i = threadIdx.x; i < n_check; i += blockDim.x)
        if (edge32[2 * i + 1] != 0) any_nonzero = 1;
    __syncthreads();
    if (threadIdx.x == 0) g_edge_is64 = (any_nonzero == 0) ? 1 : 0;
}

// ---------------------------------------------------------------------------
// Kernel 1: node GEMM. 32 nodes/block, 128 threads.
// ---------------------------------------------------------------------------
__global__ void __launch_bounds__(128) gemm_kernel(
    const float* __restrict__ ns, const float* __restrict__ W1,
    const float* __restrict__ b1, const float* __restrict__ W2,
    const float* __restrict__ b2, float* __restrict__ out_s, int N)
{
    __shared__ __align__(16) float W1s[64 * 64];
    __shared__ __align__(16) float xs[32 * 64];
    __shared__ __align__(16) float hs[32 * 64];
    __shared__ float b1s[64];
    __shared__ float b2s[192];

    int tid = threadIdx.x;
    for (int i = tid; i < 4096; i += 128) W1s[i] = W1[i];
    if (tid < 64) b1s[tid] = b1[tid];
    if (tid < 64) {
        b2s[tid] = b2[tid];
        b2s[tid + 64] = b2[tid + 64];
        b2s[tid + 128] = b2[tid + 128];
    }
    int base = blockIdx.x * 32;
    for (int i = tid; i < 32 * 64; i += 128) {
        int node = base + (i >> 6);
        float v = (node < N) ? ns[(size_t)base * 64 + i] : 0.f;
        xs[i] = v;
        if (node < N) out_s[(size_t)base * 64 + i] = v;  // residual init
    }
    __syncthreads();

    int fg = tid & 15;
    int ng = tid >> 4;
    int fb = fg * 4, n0 = ng * 4;

    float acc[4][4];
#pragma unroll
    for (int g = 0; g < 4; g++)
#pragma unroll
        for (int k = 0; k < 4; k++) acc[g][k] = 0.f;
#pragma unroll 8
    for (int i = 0; i < 64; i++) {
        float4 w = reinterpret_cast<const float4*>(W1s)[i * 16 + fg];
#pragma unroll
        for (int g = 0; g < 4; g++) {
            float x = xs[(n0 + g) * 64 + i];
            acc[g][0] = fmaf(x, w.x, acc[g][0]);
            acc[g][1] = fmaf(x, w.y, acc[g][1]);
            acc[g][2] = fmaf(x, w.z, acc[g][2]);
            acc[g][3] = fmaf(x, w.w, acc[g][3]);
        }
    }
#pragma unroll
    for (int g = 0; g < 4; g++) {
        float4 hv;
        float* hp = (float*)&hv;
#pragma unroll
        for (int k = 0; k < 4; k++) {
            float v = acc[g][k] + b1s[fb + k];
            hp[k] = v / (1.f + __expf(-v));
        }
        reinterpret_cast<float4*>(&hs[(n0 + g) * 64 + fb])[0] = hv;
    }
    __syncthreads();

#pragma unroll 1
    for (int p = 0; p < 3; p++) {
#pragma unroll
        for (int g = 0; g < 4; g++)
#pragma unroll
            for (int k = 0; k < 4; k++) acc[g][k] = 0.f;
#pragma unroll 8
        for (int i = 0; i < 64; i++) {
            float4 w = __ldg(reinterpret_cast<const float4*>(W2) + i * 48 + p * 16 + fg);
#pragma unroll
            for (int g = 0; g < 4; g++) {
                float h = hs[(n0 + g) * 64 + i];
                acc[g][0] = fmaf(h, w.x, acc[g][0]);
                acc[g][1] = fmaf(h, w.y, acc[g][1]);
                acc[g][2] = fmaf(h, w.z, acc[g][2]);
                acc[g][3] = fmaf(h, w.w, acc[g][3]);
            }
        }
#pragma unroll
        for (int g = 0; g < 4; g++) {
            int node = base + n0 + g;
            if (node < N) {
                float4 ov;
                float* op = (float*)&ov;
#pragma unroll
                for (int k = 0; k < 4; k++) op[k] = acc[g][k] + b2s[p * 64 + fb + k];
                reinterpret_cast<float4*>(&g_so[(size_t)node * 192 + p * 64 + fb])[0] = ov;
            }
        }
    }
}

// ---------------------------------------------------------------------------
// Kernel 2: init vector half of output
// ---------------------------------------------------------------------------
__global__ void copy_vec_kernel(const float4* __restrict__ src,
                                float4* __restrict__ dst, int n4)
{
    int i = blockIdx.x * blockDim.x + threadIdx.x;
    if (i < n4) dst[i] = src[i];
}

// ---------------------------------------------------------------------------
// Kernel 3: edge kernel. 192 threads (thread = feature), 32 edges per tile,
// 6 blocks/SM target.
// ---------------------------------------------------------------------------
__global__ void __launch_bounds__(192, 6) edge_kernel(
    const void* __restrict__ edge_raw, const float* __restrict__ ediff,
    const float* __restrict__ edist, const float* __restrict__ Wf,
    const float* __restrict__ bf, const float* __restrict__ nv,
    float* __restrict__ out_s, float* __restrict__ out_v,
    int E, int ntiles)
{
    __shared__ __align__(16) float rbf_s[20 * 32];  // [n][e]
    __shared__ __align__(16) float fo_s[32 * 192];  // [e][f]
    __shared__ float cut_s[32];
    __shared__ float unit_s[3 * 32];                // [d3][e]
    __shared__ int src_s[32], dst_s[32];

    int tid = threadIdx.x;  // = feature f, 0..191
    int is64 = g_edge_is64;
    const int* e32 = (const int*)edge_raw;
    const long long* e64 = (const long long*)edge_raw;

    // Wf column for this feature as 20 scalar floats (packed per use)
    float wf[20];
#pragma unroll
    for (int n = 0; n < 20; n++) wf[n] = __ldg(&Wf[n * 192 + tid]);
    float bf_r = __ldg(&bf[tid]);

    int c = tid & 63;   // vector channel
    int d3 = tid >> 6;  // vector component 0..2 (constant per warp)

    for (int t = blockIdx.x; t < ntiles; t += gridDim.x) {
        int ebase = t * 32;
        __syncthreads();  // protect smem from previous iteration's readers

        // meta load (warp 0)
        if (tid < 32) {
            int e = ebase + tid;
            if (e < E) {
                float d = __ldg(&edist[e]);
                float inv = __fdividef(1.f, d);
                cut_s[tid] = (d < CUTOFF_F) ? 0.5f * (__cosf((PI_F / CUTOFF_F) * d) + 1.f) : 0.f;
                int sv, dv;
                if (is64) {
                    dv = (int)e64[2 * (size_t)e + 0];
                    sv = (int)e64[2 * (size_t)e + 1];
                } else {
                    dv = e32[2 * (size_t)e + 0];
                    sv = e32[2 * (size_t)e + 1];
                }
                src_s[tid] = sv;
                dst_s[tid] = dv;
                unit_s[0 * 32 + tid] = __ldg(&ediff[3 * (size_t)e + 0]) * inv;
                unit_s[1 * 32 + tid] = __ldg(&ediff[3 * (size_t)e + 1]) * inv;
                unit_s[2 * 32 + tid] = __ldg(&ediff[3 * (size_t)e + 2]) * inv;
            } else {
                cut_s[tid] = 0.f;
                src_s[tid] = 0; dst_s[tid] = 0;
                unit_s[tid] = unit_s[32 + tid] = unit_s[64 + tid] = 0.f;
            }
        }
        // rbf (all threads; reads edist directly so no barrier vs meta phase)
        for (int idx = tid; idx < 640; idx += 192) {
            int n = idx >> 5, e = idx & 31;
            int ge = ebase + e;
            float d = (ge < E) ? __ldg(&edist[ge]) : 1.f;
            rbf_s[idx] = __fdividef(__sinf(d * ((float)(n + 1) * (PI_F / CUTOFF_F))), d);
        }
        __syncthreads();

        // filter = (rbf @ Wf + bf) * cut * scalar_out[src], two halves of 16 edges
#pragma unroll 1
        for (int half = 0; half < 2; half++) {
            unsigned long long a01[4], a23[4];
#pragma unroll
            for (int g = 0; g < 4; g++) { a01[g] = 0ull; a23[g] = 0ull; }
#pragma unroll
            for (int n = 0; n < 20; n++) {
                unsigned long long w2 = pack2(wf[n]);
#pragma unroll
                for (int g = 0; g < 4; g++) {
                    ulonglong2 rr = *reinterpret_cast<const ulonglong2*>(
                        &rbf_s[n * 32 + half * 16 + g * 4]);
                    a01[g] = fma2(rr.x, w2, a01[g]);
                    a23[g] = fma2(rr.y, w2, a23[g]);
                }
            }
#pragma unroll
            for (int g = 0; g < 4; g++) {
                float fv[4];
                fv[0] = __uint_as_float((unsigned)a01[g]);
                fv[1] = __uint_as_float((unsigned)(a01[g] >> 32));
                fv[2] = __uint_as_float((unsigned)a23[g]);
                fv[3] = __uint_as_float((unsigned)(a23[g] >> 32));
#pragma unroll
                for (int j = 0; j < 4; j++) {
                    int e = half * 16 + g * 4 + j;
                    float sov = __ldg(&g_so[(unsigned)src_s[e] * 192u + tid]);
                    fo_s[e * 192 + tid] = (fv[j] + bf_r) * cut_s[e] * sov;
                }
            }
        }
        __syncthreads();

        // vector messages + scatter-add
#pragma unroll 8
        for (int e = 0; e < 32; e++) {
            int src = src_s[e], dst = dst_s[e];
            float gs = fo_s[e * 192 + c];
            float ge = fo_s[e * 192 + 64 + c];
            float u = unit_s[d3 * 32 + e];
            float nvv = __ldg(&nv[(unsigned)src * 192u + d3 * 64 + c]);
            atomicAdd(&out_v[(unsigned)dst * 192u + d3 * 64 + c], fmaf(nvv, gs, ge * u));
        }
        // scalar messages: 2048 atomics spread over all 192 threads
#pragma unroll
        for (int idx = tid; idx < 2048; idx += 192) {
            int e = idx >> 6, f = idx & 63;
            atomicAdd(&out_s[(unsigned)dst_s[e] * 64u + f], fo_s[e * 192 + 128 + f]);
        }
    }
}

// ---------------------------------------------------------------------------
extern "C" void kernel_launch(void* const* d_in, const int* in_sizes, int n_in,
                              void* d_out, int out_size)
{
    const float* ns     = (const float*)d_in[0];
    const float* nvec   = (const float*)d_in[1];
    const void*  ed     = (const void*)d_in[2];
    const float* ediff  = (const float*)d_in[3];
    const float* edist  = (const float*)d_in[4];
    const float* W1     = (const float*)d_in[5];
    const float* b1     = (const float*)d_in[6];
    const float* W2     = (const float*)d_in[7];
    const float* b2     = (const float*)d_in[8];
    const float* Wf     = (const float*)d_in[9];
    const float* bf     = (const float*)d_in[10];

    int N = in_sizes[0] / 64;
    int E = in_sizes[4];  // edge_dist has E elements

    float* out_s = (float*)d_out;
    float* out_v = out_s + (size_t)N * 64;

    // 0) detect edge index dtype (int32 vs int64)
    int n_check = (E < 1024) ? E : 1024;
    detect_kernel<<<1, 256>>>((const int*)ed, n_check);

    // 1) node MLP (+ scalar residual init)
    gemm_kernel<<<(N + 31) / 32, 128>>>(ns, W1, b1, W2, b2, out_s, N);

    // 2) vector residual init
    int n4 = (N * 192) / 4;
    copy_vec_kernel<<<(n4 + 255) / 256, 256>>>(
        (const float4*)nvec, (float4*)out_v, n4);

    // 3) edge messages + scatter
    int ntiles = (E + 31) / 32;
    int grid = ntiles < 888 ? ntiles : 888;
    edge_kernel<<<grid, 192>>>(ed, ediff, edist, Wf, bf, nvec,
                               out_s, out_v, E, ntiles);
}

// round 4
// speedup vs baseline: 1.3768x; 1.0078x over previous
#include <cuda_runtime.h>
#include <cstdint>

#define PI_F 3.14159265358979323846f
#define CUTOFF_F 5.0f
#define MAX_N 50000

// scratch for scalar_out = silu(ns@W1+b1)@W2+b2, shape [N,192]
__device__ float g_so[(size_t)MAX_N * 192];
__device__ int g_edge_is64;

// packed f32x2 fma
__device__ __forceinline__ unsigned long long fma2(unsigned long long a,
                                                   unsigned long long b,
                                                   unsigned long long c) {
    unsigned long long d;
    asm("fma.rn.f32x2 %0, %1, %2, %3;" : "=l"(d) : "l"(a), "l"(b), "l"(c));
    return d;
}

__device__ __forceinline__ unsigned long long pack2(float w) {
    unsigned long long r;
    asm("mov.b64 %0, {%1, %1};" : "=l"(r) : "f"(w));
    return r;
}

// vectorized global reduction (sm_90+)
__device__ __forceinline__ void red_v4(float* p, float a, float b, float c, float d) {
    asm volatile("red.global.add.v4.f32 [%0], {%1, %2, %3, %4};"
                 :: "l"(p), "f"(a), "f"(b), "f"(c), "f"(d) : "memory");
}

// ---------------------------------------------------------------------------
// Kernel 0: detect whether edge array is int64 (odd int32 words all zero)
// ---------------------------------------------------------------------------
__global__ void detect_kernel(const int* __restrict__ edge32, int n_check)
{
    __shared__ int any_nonzero;
    if (threadIdx.x == 0) any_nonzero = 0;
    __syncthreads();
    for (int i = threadIdx.x; i < n_check; i += blockDim.x)
        if (edge32[2 * i + 1] != 0) any_nonzero = 1;
    __syncthreads();
    if (threadIdx.x == 0) g_edge_is64 = (any_nonzero == 0) ? 1 : 0;
}

// ---------------------------------------------------------------------------
// Kernel 1: node GEMM. 32 nodes/block, 128 threads.
// ---------------------------------------------------------------------------
__global__ void __launch_bounds__(128) gemm_kernel(
    const float* __restrict__ ns, const float* __restrict__ W1,
    const float* __restrict__ b1, const float* __restrict__ W2,
    const float* __restrict__ b2, float* __restrict__ out_s, int N)
{
    __shared__ __align__(16) float W1s[64 * 64];
    __shared__ __align__(16) float xs[32 * 64];
    __shared__ __align__(16) float hs[32 * 64];
    __shared__ float b1s[64];
    __shared__ float b2s[192];

    int tid = threadIdx.x;
    for (int i = tid; i < 4096; i += 128) W1s[i] = W1[i];
    if (tid < 64) b1s[tid] = b1[tid];
    if (tid < 64) {
        b2s[tid] = b2[tid];
        b2s[tid + 64] = b2[tid + 64];
        b2s[tid + 128] = b2[tid + 128];
    }
    int base = blockIdx.x * 32;
    for (int i = tid; i < 32 * 64; i += 128) {
        int node = base + (i >> 6);
        float v = (node < N) ? ns[(size_t)base * 64 + i] : 0.f;
        xs[i] = v;
        if (node < N) out_s[(size_t)base * 64 + i] = v;  // residual init
    }
    __syncthreads();

    int fg = tid & 15;
    int ng = tid >> 4;
    int fb = fg * 4, n0 = ng * 4;

    float acc[4][4];
#pragma unroll
    for (int g = 0; g < 4; g++)
#pragma unroll
        for (int k = 0; k < 4; k++) acc[g][k] = 0.f;
#pragma unroll 8
    for (int i = 0; i < 64; i++) {
        float4 w = reinterpret_cast<const float4*>(W1s)[i * 16 + fg];
#pragma unroll
        for (int g = 0; g < 4; g++) {
            float x = xs[(n0 + g) * 64 + i];
            acc[g][0] = fmaf(x, w.x, acc[g][0]);
            acc[g][1] = fmaf(x, w.y, acc[g][1]);
            acc[g][2] = fmaf(x, w.z, acc[g][2]);
            acc[g][3] = fmaf(x, w.w, acc[g][3]);
        }
    }
#pragma unroll
    for (int g = 0; g < 4; g++) {
        float4 hv;
        float* hp = (float*)&hv;
#pragma unroll
        for (int k = 0; k < 4; k++) {
            float v = acc[g][k] + b1s[fb + k];
            hp[k] = v / (1.f + __expf(-v));
        }
        reinterpret_cast<float4*>(&hs[(n0 + g) * 64 + fb])[0] = hv;
    }
    __syncthreads();

#pragma unroll 1
    for (int p = 0; p < 3; p++) {
#pragma unroll
        for (int g = 0; g < 4; g++)
#pragma unroll
            for (int k = 0; k < 4; k++) acc[g][k] = 0.f;
#pragma unroll 8
        for (int i = 0; i < 64; i++) {
            float4 w = __ldg(reinterpret_cast<const float4*>(W2) + i * 48 + p * 16 + fg);
#pragma unroll
            for (int g = 0; g < 4; g++) {
                float h = hs[(n0 + g) * 64 + i];
                acc[g][0] = fmaf(h, w.x, acc[g][0]);
                acc[g][1] = fmaf(h, w.y, acc[g][1]);
                acc[g][2] = fmaf(h, w.z, acc[g][2]);
                acc[g][3] = fmaf(h, w.w, acc[g][3]);
            }
        }
#pragma unroll
        for (int g = 0; g < 4; g++) {
            int node = base + n0 + g;
            if (node < N) {
                float4 ov;
                float* op = (float*)&ov;
#pragma unroll
                for (int k = 0; k < 4; k++) op[k] = acc[g][k] + b2s[p * 64 + fb + k];
                reinterpret_cast<float4*>(&g_so[(size_t)node * 192 + p * 64 + fb])[0] = ov;
            }
        }
    }
}

// ---------------------------------------------------------------------------
// Kernel 2: init vector half of output
// ---------------------------------------------------------------------------
__global__ void copy_vec_kernel(const float4* __restrict__ src,
                                float4* __restrict__ dst, int n4)
{
    int i = blockIdx.x * blockDim.x + threadIdx.x;
    if (i < n4) dst[i] = src[i];
}

// ---------------------------------------------------------------------------
// Kernel 3: edge kernel. 192 threads (thread = feature), 32 edges per tile.
// ---------------------------------------------------------------------------
__global__ void __launch_bounds__(192, 6) edge_kernel(
    const void* __restrict__ edge_raw, const float* __restrict__ ediff,
    const float* __restrict__ edist, const float* __restrict__ Wf,
    const float* __restrict__ bf, const float* __restrict__ nv,
    float* __restrict__ out_s, float* __restrict__ out_v,
    int E, int ntiles)
{
    __shared__ __align__(16) float rbf_s[20 * 32];  // [n][e]
    __shared__ __align__(16) float fo_s[32 * 192];  // [e][f] = filter*cut*sov
    __shared__ float cut_s[32];
    __shared__ float unit_s[3 * 32];                // [d3][e]
    __shared__ int src_s[32], dst_s[32];

    int tid = threadIdx.x;  // = feature f, 0..191
    int is64 = g_edge_is64;
    const int* e32 = (const int*)edge_raw;
    const long long* e64 = (const long long*)edge_raw;

    float wf[20];
#pragma unroll
    for (int n = 0; n < 20; n++) wf[n] = __ldg(&Wf[n * 192 + tid]);
    float bf_r = __ldg(&bf[tid]);

    // quad decomposition for the message phase
    int q    = tid % 48;     // quad within edge (features 4q..4q+3)
    int esub = tid / 48;     // 0..3
    int j0 = q * 4;          // flat feature base
    int d3 = j0 >> 6;        // vector component
    int c4 = j0 & 63;        // channel base (multiple of 4)

    for (int t = blockIdx.x; t < ntiles; t += gridDim.x) {
        int ebase = t * 32;
        __syncthreads();  // protect smem from previous iteration's readers

        // meta load (warp 0)
        if (tid < 32) {
            int e = ebase + tid;
            if (e < E) {
                float d = __ldg(&edist[e]);
                float inv = __fdividef(1.f, d);
                cut_s[tid] = (d < CUTOFF_F) ? 0.5f * (__cosf((PI_F / CUTOFF_F) * d) + 1.f) : 0.f;
                int sv, dv;
                if (is64) {
                    dv = (int)e64[2 * (size_t)e + 0];
                    sv = (int)e64[2 * (size_t)e + 1];
                } else {
                    dv = e32[2 * (size_t)e + 0];
                    sv = e32[2 * (size_t)e + 1];
                }
                src_s[tid] = sv;
                dst_s[tid] = dv;
                unit_s[0 * 32 + tid] = __ldg(&ediff[3 * (size_t)e + 0]) * inv;
                unit_s[1 * 32 + tid] = __ldg(&ediff[3 * (size_t)e + 1]) * inv;
                unit_s[2 * 32 + tid] = __ldg(&ediff[3 * (size_t)e + 2]) * inv;
            } else {
                cut_s[tid] = 0.f;
                src_s[tid] = 0; dst_s[tid] = 0;
                unit_s[tid] = unit_s[32 + tid] = unit_s[64 + tid] = 0.f;
            }
        }
        // rbf (all threads)
        for (int idx = tid; idx < 640; idx += 192) {
            int n = idx >> 5, e = idx & 31;
            int ge = ebase + e;
            float d = (ge < E) ? __ldg(&edist[ge]) : 1.f;
            rbf_s[idx] = __fdividef(__sinf(d * ((float)(n + 1) * (PI_F / CUTOFF_F))), d);
        }
        __syncthreads();

        // fo = (rbf @ Wf + bf) * cut * scalar_out[src]
#pragma unroll 1
        for (int half = 0; half < 2; half++) {
            unsigned long long a01[4], a23[4];
#pragma unroll
            for (int g = 0; g < 4; g++) { a01[g] = 0ull; a23[g] = 0ull; }
#pragma unroll
            for (int n = 0; n < 20; n++) {
                unsigned long long w2 = pack2(wf[n]);
#pragma unroll
                for (int g = 0; g < 4; g++) {
                    ulonglong2 rr = *reinterpret_cast<const ulonglong2*>(
                        &rbf_s[n * 32 + half * 16 + g * 4]);
                    a01[g] = fma2(rr.x, w2, a01[g]);
                    a23[g] = fma2(rr.y, w2, a23[g]);
                }
            }
#pragma unroll
            for (int g = 0; g < 4; g++) {
                float fv[4];
                fv[0] = __uint_as_float((unsigned)a01[g]);
                fv[1] = __uint_as_float((unsigned)(a01[g] >> 32));
                fv[2] = __uint_as_float((unsigned)a23[g]);
                fv[3] = __uint_as_float((unsigned)(a23[g] >> 32));
#pragma unroll
                for (int j = 0; j < 4; j++) {
                    int e = half * 16 + g * 4 + j;
                    float sov = __ldg(&g_so[(unsigned)src_s[e] * 192u + tid]);
                    fo_s[e * 192 + tid] = (fv[j] + bf_r) * cut_s[e] * sov;
                }
            }
        }
        __syncthreads();

        // vector messages: 4 edges in parallel x 8 iterations, v4 atomics
#pragma unroll 2
        for (int it = 0; it < 8; it++) {
            int e = it * 4 + esub;
            int src = src_s[e], dst = dst_s[e];
            float4 gs = *reinterpret_cast<const float4*>(&fo_s[e * 192 + c4]);
            float4 ge = *reinterpret_cast<const float4*>(&fo_s[e * 192 + 64 + c4]);
            float u = unit_s[d3 * 32 + e];
            float4 nvq = __ldg(reinterpret_cast<const float4*>(
                &nv[(unsigned)src * 192u + d3 * 64 + c4]));
            float mx = fmaf(nvq.x, gs.x, ge.x * u);
            float my = fmaf(nvq.y, gs.y, ge.y * u);
            float mz = fmaf(nvq.z, gs.z, ge.z * u);
            float mw = fmaf(nvq.w, gs.w, ge.w * u);
            red_v4(&out_v[(unsigned)dst * 192u + d3 * 64 + c4], mx, my, mz, mw);
        }
        // scalar messages: 512 quads over 192 threads, v4 atomics
#pragma unroll 1
        for (int idx = tid; idx < 512; idx += 192) {
            int e = idx >> 4, f4 = (idx & 15) * 4;
            float4 m = *reinterpret_cast<const float4*>(&fo_s[e * 192 + 128 + f4]);
            red_v4(&out_s[(unsigned)dst_s[e] * 64u + f4], m.x, m.y, m.z, m.w);
        }
    }
}

// ---------------------------------------------------------------------------
extern "C" void kernel_launch(void* const* d_in, const int* in_sizes, int n_in,
                              void* d_out, int out_size)
{
    const float* ns     = (const float*)d_in[0];
    const float* nvec   = (const float*)d_in[1];
    const void*  ed     = (const void*)d_in[2];
    const float* ediff  = (const float*)d_in[3];
    const float* edist  = (const float*)d_in[4];
    const float* W1     = (const float*)d_in[5];
    const float* b1     = (const float*)d_in[6];
    const float* W2     = (const float*)d_in[7];
    const float* b2     = (const float*)d_in[8];
    const float* Wf     = (const float*)d_in[9];
    const float* bf     = (const float*)d_in[10];

    int N = in_sizes[0] / 64;
    int E = in_sizes[4];  // edge_dist has E elements

    float* out_s = (float*)d_out;
    float* out_v = out_s + (size_t)N * 64;

    // 0) detect edge index dtype (int32 vs int64)
    int n_check = (E < 1024) ? E : 1024;
    detect_kernel<<<1, 256>>>((const int*)ed, n_check);

    // 1) node MLP (+ scalar residual init)
    gemm_kernel<<<(N + 31) / 32, 128>>>(ns, W1, b1, W2, b2, out_s, N);

    // 2) vector residual init
    int n4 = (N * 192) / 4;
    copy_vec_kernel<<<(n4 + 255) / 256, 256>>>(
        (const float4*)nvec, (float4*)out_v, n4);

    // 3) edge messages + scatter
    int ntiles = (E + 31) / 32;
    int grid = ntiles < 888 ? ntiles : 888;
    edge_kernel<<<grid, 192>>>(ed, ediff, edist, Wf, bf, nvec,
                               out_s, out_v, E, ntiles);
}

// round 5
// speedup vs baseline: 1.8093x; 1.3141x over previous
#include <cuda_runtime.h>
#include <cstdint>

#define PI_F 3.14159265358979323846f
#define CUTOFF_F 5.0f
#define MAX_N 50000

// scratch for scalar_out = silu(ns@W1+b1)@W2+b2, shape [N,192]
__device__ float g_so[(size_t)MAX_N * 192];
__device__ int g_edge_is64;

// packed f32x2 fma
__device__ __forceinline__ unsigned long long fma2(unsigned long long a,
                                                   unsigned long long b,
                                                   unsigned long long c) {
    unsigned long long d;
    asm("fma.rn.f32x2 %0, %1, %2, %3;" : "=l"(d) : "l"(a), "l"(b), "l"(c));
    return d;
}

__device__ __forceinline__ unsigned long long pack2(float w) {
    unsigned long long r;
    asm("mov.b64 %0, {%1, %1};" : "=l"(r) : "f"(w));
    return r;
}

// ---------------------------------------------------------------------------
// Kernel 0: detect whether edge array is int64 (odd int32 words all zero)
// ---------------------------------------------------------------------------
__global__ void detect_kernel(const int* __restrict__ edge32, int n_check)
{
    __shared__ int any_nonzero;
    if (threadIdx.x == 0) any_nonzero = 0;
    __syncthreads();
    for (int i = threadIdx.x; i < n_check; i += blockDim.x)
        if (edge32[2 * i + 1] != 0) any_nonzero = 1;
    __syncthreads();
    if (threadIdx.x == 0) g_edge_is64 = (any_nonzero == 0) ? 1 : 0;
}

// ---------------------------------------------------------------------------
// Kernel 1: node GEMM. 32 nodes/block, 128 threads.
// ---------------------------------------------------------------------------
__global__ void __launch_bounds__(128) gemm_kernel(
    const float* __restrict__ ns, const float* __restrict__ W1,
    const float* __restrict__ b1, const float* __restrict__ W2,
    const float* __restrict__ b2, float* __restrict__ out_s, int N)
{
    __shared__ __align__(16) float W1s[64 * 64];
    __shared__ __align__(16) float xs[32 * 64];
    __shared__ __align__(16) float hs[32 * 64];
    __shared__ float b1s[64];
    __shared__ float b2s[192];

    int tid = threadIdx.x;
    for (int i = tid; i < 4096; i += 128) W1s[i] = W1[i];
    if (tid < 64) b1s[tid] = b1[tid];
    if (tid < 64) {
        b2s[tid] = b2[tid];
        b2s[tid + 64] = b2[tid + 64];
        b2s[tid + 128] = b2[tid + 128];
    }
    int base = blockIdx.x * 32;
    for (int i = tid; i < 32 * 64; i += 128) {
        int node = base + (i >> 6);
        float v = (node < N) ? ns[(size_t)base * 64 + i] : 0.f;
        xs[i] = v;
        if (node < N) out_s[(size_t)base * 64 + i] = v;  // residual init
    }
    __syncthreads();

    int fg = tid & 15;
    int ng = tid >> 4;
    int fb = fg * 4, n0 = ng * 4;

    float acc[4][4];
#pragma unroll
    for (int g = 0; g < 4; g++)
#pragma unroll
        for (int k = 0; k < 4; k++) acc[g][k] = 0.f;
#pragma unroll 8
    for (int i = 0; i < 64; i++) {
        float4 w = reinterpret_cast<const float4*>(W1s)[i * 16 + fg];
#pragma unroll
        for (int g = 0; g < 4; g++) {
            float x = xs[(n0 + g) * 64 + i];
            acc[g][0] = fmaf(x, w.x, acc[g][0]);
            acc[g][1] = fmaf(x, w.y, acc[g][1]);
            acc[g][2] = fmaf(x, w.z, acc[g][2]);
            acc[g][3] = fmaf(x, w.w, acc[g][3]);
        }
    }
#pragma unroll
    for (int g = 0; g < 4; g++) {
        float4 hv;
        float* hp = (float*)&hv;
#pragma unroll
        for (int k = 0; k < 4; k++) {
            float v = acc[g][k] + b1s[fb + k];
            hp[k] = v / (1.f + __expf(-v));
        }
        reinterpret_cast<float4*>(&hs[(n0 + g) * 64 + fb])[0] = hv;
    }
    __syncthreads();

#pragma unroll 1
    for (int p = 0; p < 3; p++) {
#pragma unroll
        for (int g = 0; g < 4; g++)
#pragma unroll
            for (int k = 0; k < 4; k++) acc[g][k] = 0.f;
#pragma unroll 8
        for (int i = 0; i < 64; i++) {
            float4 w = __ldg(reinterpret_cast<const float4*>(W2) + i * 48 + p * 16 + fg);
#pragma unroll
            for (int g = 0; g < 4; g++) {
                float h = hs[(n0 + g) * 64 + i];
                acc[g][0] = fmaf(h, w.x, acc[g][0]);
                acc[g][1] = fmaf(h, w.y, acc[g][1]);
                acc[g][2] = fmaf(h, w.z, acc[g][2]);
                acc[g][3] = fmaf(h, w.w, acc[g][3]);
            }
        }
#pragma unroll
        for (int g = 0; g < 4; g++) {
            int node = base + n0 + g;
            if (node < N) {
                float4 ov;
                float* op = (float*)&ov;
#pragma unroll
                for (int k = 0; k < 4; k++) op[k] = acc[g][k] + b2s[p * 64 + fb + k];
                reinterpret_cast<float4*>(&g_so[(size_t)node * 192 + p * 64 + fb])[0] = ov;
            }
        }
    }
}

// ---------------------------------------------------------------------------
// Kernel 2: init vector half of output
// ---------------------------------------------------------------------------
__global__ void copy_vec_kernel(const float4* __restrict__ src,
                                float4* __restrict__ dst, int n4)
{
    int i = blockIdx.x * blockDim.x + threadIdx.x;
    if (i < n4) dst[i] = src[i];
}

// ---------------------------------------------------------------------------
// Kernel 3: edge kernel. 192 threads, 32 edges per tile.
// Warp roles: wid 0-3 handle gs/ge feature pairs (c, 64+c) for 16 edges each;
// wid 4-5 handle ms features (128..191) for all 32 edges. No fo_s staging.
// ---------------------------------------------------------------------------
__global__ void __launch_bounds__(192, 5) edge_kernel(
    const void* __restrict__ edge_raw, const float* __restrict__ ediff,
    const float* __restrict__ edist, const float* __restrict__ Wf,
    const float* __restrict__ bf, const float* __restrict__ nv,
    float* __restrict__ out_s, float* __restrict__ out_v,
    int E, int ntiles)
{
    __shared__ __align__(16) float rbf_s[20 * 32];  // [n][e]
    __shared__ __align__(16) float unit_s[3 * 32];  // [d3][e]
    __shared__ __align__(16) float cut_s[32];
    __shared__ int src_s[32], dst_s[32];

    int tid  = threadIdx.x;
    int wid  = tid >> 5;
    int lane = tid & 31;
    int is64 = g_edge_is64;
    const int* e32 = (const int*)edge_raw;
    const long long* e64 = (const long long*)edge_raw;

    bool is_vec = (wid < 4);
    // vector warps: channel c, edges [eoff, eoff+16)
    int c    = ((wid & 1) << 5) + lane;     // 0..63
    int eoff = (wid & 2) ? 16 : 0;
    // scalar warps: feature index 128 + fs
    int fs   = ((wid - 4) << 5) + lane;     // 0..63 (valid when wid>=4)

    // weights: vector threads need columns c and 64+c; scalar threads 128+fs
    float wfA[20], wfB[20];
    float bfA, bfB;
    if (is_vec) {
#pragma unroll
        for (int n = 0; n < 20; n++) {
            wfA[n] = __ldg(&Wf[n * 192 + c]);
            wfB[n] = __ldg(&Wf[n * 192 + 64 + c]);
        }
        bfA = __ldg(&bf[c]);
        bfB = __ldg(&bf[64 + c]);
    } else {
#pragma unroll
        for (int n = 0; n < 20; n++) wfA[n] = __ldg(&Wf[n * 192 + 128 + fs]);
        bfA = __ldg(&bf[128 + fs]);
        bfB = 0.f;
#pragma unroll
        for (int n = 0; n < 20; n++) wfB[n] = 0.f;
    }

    for (int t = blockIdx.x; t < ntiles; t += gridDim.x) {
        int ebase = t * 32;
        __syncthreads();  // protect smem from previous tile's readers

        // meta (warp 0) + rbf (all threads)
        if (tid < 32) {
            int e = ebase + tid;
            if (e < E) {
                float d = __ldg(&edist[e]);
                float inv = __fdividef(1.f, d);
                cut_s[tid] = (d < CUTOFF_F) ? 0.5f * (__cosf((PI_F / CUTOFF_F) * d) + 1.f) : 0.f;
                int sv, dv;
                if (is64) {
                    dv = (int)e64[2 * (size_t)e + 0];
                    sv = (int)e64[2 * (size_t)e + 1];
                } else {
                    dv = e32[2 * (size_t)e + 0];
                    sv = e32[2 * (size_t)e + 1];
                }
                src_s[tid] = sv;
                dst_s[tid] = dv;
                unit_s[0 * 32 + tid] = __ldg(&ediff[3 * (size_t)e + 0]) * inv;
                unit_s[1 * 32 + tid] = __ldg(&ediff[3 * (size_t)e + 1]) * inv;
                unit_s[2 * 32 + tid] = __ldg(&ediff[3 * (size_t)e + 2]) * inv;
            } else {
                cut_s[tid] = 0.f;
                src_s[tid] = 0; dst_s[tid] = 0;
                unit_s[tid] = unit_s[32 + tid] = unit_s[64 + tid] = 0.f;
            }
        }
        for (int idx = tid; idx < 640; idx += 192) {
            int n = idx >> 5, e = idx & 31;
            int ge = ebase + e;
            float d = (ge < E) ? __ldg(&edist[ge]) : 1.f;
            rbf_s[idx] = __fdividef(__sinf(d * ((float)(n + 1) * (PI_F / CUTOFF_F))), d);
        }
        __syncthreads();

        if (is_vec) {
            // 4 groups of 4 edges within this warp's 16-edge slice
#pragma unroll 1
            for (int g = 0; g < 4; g++) {
                unsigned long long a01 = 0ull, a23 = 0ull;
                unsigned long long b01 = 0ull, b23 = 0ull;
#pragma unroll
                for (int n = 0; n < 20; n++) {
                    ulonglong2 rr = *reinterpret_cast<const ulonglong2*>(
                        &rbf_s[n * 32 + eoff + g * 4]);
                    unsigned long long wA = pack2(wfA[n]);
                    unsigned long long wB = pack2(wfB[n]);
                    a01 = fma2(rr.x, wA, a01);
                    a23 = fma2(rr.y, wA, a23);
                    b01 = fma2(rr.x, wB, b01);
                    b23 = fma2(rr.y, wB, b23);
                }
                float fa[4], fb[4];
                fa[0] = __uint_as_float((unsigned)a01);
                fa[1] = __uint_as_float((unsigned)(a01 >> 32));
                fa[2] = __uint_as_float((unsigned)a23);
                fa[3] = __uint_as_float((unsigned)(a23 >> 32));
                fb[0] = __uint_as_float((unsigned)b01);
                fb[1] = __uint_as_float((unsigned)(b01 >> 32));
                fb[2] = __uint_as_float((unsigned)b23);
                fb[3] = __uint_as_float((unsigned)(b23 >> 32));
#pragma unroll
                for (int j = 0; j < 4; j++) {
                    int e = eoff + g * 4 + j;
                    int src = src_s[e], dst = dst_s[e];
                    float cut = cut_s[e];
                    float gs = (fa[j] + bfA) * cut * __ldg(&g_so[(unsigned)src * 192u + c]);
                    float ge = (fb[j] + bfB) * cut * __ldg(&g_so[(unsigned)src * 192u + 64 + c]);
#pragma unroll
                    for (int d3 = 0; d3 < 3; d3++) {
                        float u = unit_s[d3 * 32 + e];
                        float nvv = __ldg(&nv[(unsigned)src * 192u + d3 * 64 + c]);
                        atomicAdd(&out_v[(unsigned)dst * 192u + d3 * 64 + c],
                                  fmaf(nvv, gs, ge * u));
                    }
                }
            }
        } else {
            // scalar warps: 8 groups of 4 edges, all 32 edges
#pragma unroll 1
            for (int g = 0; g < 8; g++) {
                unsigned long long a01 = 0ull, a23 = 0ull;
#pragma unroll
                for (int n = 0; n < 20; n++) {
                    ulonglong2 rr = *reinterpret_cast<const ulonglong2*>(
                        &rbf_s[n * 32 + g * 4]);
                    unsigned long long wA = pack2(wfA[n]);
                    a01 = fma2(rr.x, wA, a01);
                    a23 = fma2(rr.y, wA, a23);
                }
                float fa[4];
                fa[0] = __uint_as_float((unsigned)a01);
                fa[1] = __uint_as_float((unsigned)(a01 >> 32));
                fa[2] = __uint_as_float((unsigned)a23);
                fa[3] = __uint_as_float((unsigned)(a23 >> 32));
#pragma unroll
                for (int j = 0; j < 4; j++) {
                    int e = g * 4 + j;
                    int src = src_s[e], dst = dst_s[e];
                    float ms = (fa[j] + bfA) * cut_s[e] *
                               __ldg(&g_so[(unsigned)src * 192u + 128 + fs]);
                    atomicAdd(&out_s[(unsigned)dst * 64u + fs], ms);
                }
            }
        }
    }
}

// ---------------------------------------------------------------------------
extern "C" void kernel_launch(void* const* d_in, const int* in_sizes, int n_in,
                              void* d_out, int out_size)
{
    const float* ns     = (const float*)d_in[0];
    const float* nvec   = (const float*)d_in[1];
    const void*  ed     = (const void*)d_in[2];
    const float* ediff  = (const float*)d_in[3];
    const float* edist  = (const float*)d_in[4];
    const float* W1     = (const float*)d_in[5];
    const float* b1     = (const float*)d_in[6];
    const float* W2     = (const float*)d_in[7];
    const float* b2     = (const float*)d_in[8];
    const float* Wf     = (const float*)d_in[9];
    const float* bf     = (const float*)d_in[10];

    int N = in_sizes[0] / 64;
    int E = in_sizes[4];  // edge_dist has E elements

    float* out_s = (float*)d_out;
    float* out_v = out_s + (size_t)N * 64;

    // 0) detect edge index dtype (int32 vs int64)
    int n_check = (E < 1024) ? E : 1024;
    detect_kernel<<<1, 256>>>((const int*)ed, n_check);

    // 1) node MLP (+ scalar residual init)
    gemm_kernel<<<(N + 31) / 32, 128>>>(ns, W1, b1, W2, b2, out_s, N);

    // 2) vector residual init
    int n4 = (N * 192) / 4;
    copy_vec_kernel<<<(n4 + 255) / 256, 256>>>(
        (const float4*)nvec, (float4*)out_v, n4);

    // 3) edge messages + scatter
    int ntiles = (E + 31) / 32;
    int grid = ntiles < 740 ? ntiles : 740;
    edge_kernel<<<grid, 192>>>(ed, ediff, edist, Wf, bf, nvec,
                               out_s, out_v, E, ntiles);
}